// round 6
// baseline (speedup 1.0000x reference)
#include <cuda_runtime.h>
#include <math.h>
#include <stdint.h>

#define B 128
#define T 512
#define E 256
#define H 256
#define DA 25
#define HEADS 5
#define V 2080

typedef unsigned long long ull;

// ---------------- device scratch (static, no allocs) ----------------
__device__ float g_P[(size_t)2 * V * 1024];        // [dir][v][4H]  17MB (L2-resident)
__device__ float g_Hc[(size_t)B * T * 2 * H];      // [b][t][512]; tail stale-but-finite, masked by A=0
__device__ float g_s[B * HEADS * T];               // [b][h][t]
__device__ float g_A[B * HEADS * T];               // [b][h][t]
__device__ float g_pp[B];

__device__ __forceinline__ float sigf(float x) { return 1.0f / (1.0f + expf(-x)); }

__device__ __forceinline__ ull pack2(float lo, float hi) {
    ull r; asm("mov.b64 %0, {%1,%2};" : "=l"(r) : "f"(lo), "f"(hi)); return r;
}
__device__ __forceinline__ void unpack2(ull v, float& lo, float& hi) {
    asm("mov.b64 {%0,%1}, %2;" : "=f"(lo), "=f"(hi) : "l"(v));
}
__device__ __forceinline__ ull fma2(ull a, ull b, ull c) {
    ull d; asm("fma.rn.f32x2 %0, %1, %2, %3;" : "=l"(d) : "l"(a), "l"(b), "l"(c)); return d;
}
__device__ __forceinline__ ull add2(ull a, ull b) {
    ull d; asm("add.rn.f32x2 %0, %1, %2;" : "=l"(d) : "l"(a), "l"(b)); return d;
}
__device__ __forceinline__ uint32_t smem_u32(const void* p) {
    return (uint32_t)__cvta_generic_to_shared(p);
}
__device__ __forceinline__ uint32_t mapa_u32(uint32_t addr, uint32_t rank) {
    uint32_t r; asm("mapa.shared::cluster.u32 %0, %1, %2;" : "=r"(r) : "r"(addr), "r"(rank));
    return r;
}
__device__ __forceinline__ void st_cluster_b64(uint32_t addr, ull v) {
    asm volatile("st.shared::cluster.b64 [%0], %1;" :: "r"(addr), "l"(v) : "memory");
}
__device__ __forceinline__ void mbar_init(uint32_t addr, uint32_t count) {
    asm volatile("mbarrier.init.shared.b64 [%0], %1;" :: "r"(addr), "r"(count) : "memory");
}
__device__ __forceinline__ void mbar_arrive_remote(uint32_t addr) {
    asm volatile("mbarrier.arrive.release.cluster.shared::cluster.b64 _, [%0];" :: "r"(addr) : "memory");
}
__device__ __forceinline__ void mbar_wait(uint32_t mb, uint32_t phase) {
    uint32_t done;
    do {
        asm volatile(
            "{\n\t.reg .pred p;\n\t"
            "mbarrier.try_wait.parity.acquire.cluster.shared::cta.b64 p, [%1], %2, 0x989680;\n\t"
            "selp.b32 %0, 1, 0, p;\n\t}"
            : "=r"(done) : "r"(mb), "r"(phase) : "memory");
    } while (!done);
}
#define CLUSTER_SYNC() do { \
    asm volatile("barrier.cluster.arrive.aligned;" ::: "memory"); \
    asm volatile("barrier.cluster.wait.aligned;" ::: "memory"); \
} while (0)

// ---------------- vocab projection: P[d][v][n] = emb[v] . W_ih[n] + b[n]
__global__ void k_P(const float* __restrict__ emb,
                    const float* __restrict__ Wf, const float* __restrict__ bf,
                    const float* __restrict__ Wb, const float* __restrict__ bb)
{
    const int d = blockIdx.z;
    const float* __restrict__ Wih  = d ? Wb : Wf;
    const float* __restrict__ bias = d ? bb : bf;
    const int n0 = blockIdx.x * 64;
    const int m0 = blockIdx.y * 64;

    __shared__ float As[16][68];
    __shared__ float Bs[16][68];

    const int tid = threadIdx.x;
    const int r  = tid >> 2, kq = tid & 3;
    const int tx = tid & 15, ty = tid >> 4;
    int v = m0 + r; if (v >= V) v = 0;
    const float* __restrict__ Arow = emb + (size_t)v * E;
    const float* __restrict__ Brow = Wih + (size_t)(n0 + r) * E;

    float acc[4][4] = {};

    for (int k0 = 0; k0 < E; k0 += 16) {
        float4 av = *(const float4*)&Arow[k0 + kq * 4];
        float4 bv = *(const float4*)&Brow[k0 + kq * 4];
        As[kq * 4 + 0][r] = av.x; As[kq * 4 + 1][r] = av.y;
        As[kq * 4 + 2][r] = av.z; As[kq * 4 + 3][r] = av.w;
        Bs[kq * 4 + 0][r] = bv.x; Bs[kq * 4 + 1][r] = bv.y;
        Bs[kq * 4 + 2][r] = bv.z; Bs[kq * 4 + 3][r] = bv.w;
        __syncthreads();
        #pragma unroll
        for (int kk = 0; kk < 16; kk++) {
            float4 a  = *(const float4*)&As[kk][ty * 4];
            float4 b4 = *(const float4*)&Bs[kk][tx * 4];
            acc[0][0] = fmaf(a.x, b4.x, acc[0][0]); acc[0][1] = fmaf(a.x, b4.y, acc[0][1]);
            acc[0][2] = fmaf(a.x, b4.z, acc[0][2]); acc[0][3] = fmaf(a.x, b4.w, acc[0][3]);
            acc[1][0] = fmaf(a.y, b4.x, acc[1][0]); acc[1][1] = fmaf(a.y, b4.y, acc[1][1]);
            acc[1][2] = fmaf(a.y, b4.z, acc[1][2]); acc[1][3] = fmaf(a.y, b4.w, acc[1][3]);
            acc[2][0] = fmaf(a.z, b4.x, acc[2][0]); acc[2][1] = fmaf(a.z, b4.y, acc[2][1]);
            acc[2][2] = fmaf(a.z, b4.z, acc[2][2]); acc[2][3] = fmaf(a.z, b4.w, acc[2][3]);
            acc[3][0] = fmaf(a.w, b4.x, acc[3][0]); acc[3][1] = fmaf(a.w, b4.y, acc[3][1]);
            acc[3][2] = fmaf(a.w, b4.z, acc[3][2]); acc[3][3] = fmaf(a.w, b4.w, acc[3][3]);
        }
        __syncthreads();
    }

    float b0v = bias[n0 + tx * 4 + 0];
    float b1v = bias[n0 + tx * 4 + 1];
    float b2v = bias[n0 + tx * 4 + 2];
    float b3v = bias[n0 + tx * 4 + 3];
    const size_t pbase = (size_t)d * V * 1024;
    #pragma unroll
    for (int i = 0; i < 4; i++) {
        int m = m0 + ty * 4 + i;
        if (m < V) {
            float4 o;
            o.x = acc[i][0] + b0v; o.y = acc[i][1] + b1v;
            o.z = acc[i][2] + b2v; o.w = acc[i][3] + b3v;
            *(float4*)&g_P[pbase + (size_t)m * 1024 + n0 + tx * 4] = o;
        }
    }
}

// ---------------- persistent LSTM recurrence (cluster DSMEM exchange) ----
// 128 CTAs = 16 clusters of 8. Cluster = (dir, batch-group of 16), CTA rank = j-tile of 32.
// 256 threads: thread = (kh, bq 0..7 -> 2 batches, jp 0..15 -> j-pair). f32x2 over j.
// Smem (floats): [0..4) mbarriers(2 ull), [4..33028) W, [33028..41348) hbuf[2][16][260],
//                [41348..43908) Red.
__global__ void __launch_bounds__(256, 1) __cluster_dims__(8, 1, 1)
k_lstm(const float* __restrict__ Whf, const float* __restrict__ Whb,
       const int* __restrict__ lens, const int* __restrict__ wid)
{
    extern __shared__ float sm[];
    float* Wp = sm + 4;
    float* Hb = sm + 33028;
    ull*   Red = (ull*)(sm + 41348);
    const uint32_t smb = smem_u32(sm);
    const uint32_t mbA[2] = { smb, smb + 8 };
    const uint32_t HB_BYTES = 33028u * 4u;   // byte offset of Hb

    const int tid = threadIdx.x;
    const int bx  = blockIdx.x;
    const int jb  = bx & 7, grp = bx >> 3;
    const int d   = grp >> 3, bg = grp & 7;
    const int j0  = jb * 32, b0 = bg * 16;
    const float* __restrict__ Whh = d ? Whb : Whf;
    const float* __restrict__ P   = g_P + (size_t)d * V * 1024;

    // W_hh tile -> shared, j-pair interleaved: Wp[(g*16+(j>>1))*516 + k*2 + (j&1)]
    for (int idx = tid; idx < 32768; idx += 256) {
        int g = idx >> 13, j = (idx >> 8) & 31, k = idx & 255;
        Wp[(size_t)(g * 16 + (j >> 1)) * 516 + k * 2 + (j & 1)] =
            Whh[(size_t)(g * H + j0 + j) * H + k];
    }
    // zero h buffer 0 (initial state)
    for (int idx = tid; idx < 4160; idx += 256) Hb[idx] = 0.0f;
    if (tid == 0) { mbar_init(mbA[0], 8); mbar_init(mbA[1], 8); }
    __syncthreads();
    CLUSTER_SYNC();   // mbarriers + hbuf visible cluster-wide before any remote op

    const int kh = tid >> 7, tl = tid & 127;
    const int jp = tl & 15, bq = tl >> 4;
    const int lA = bq * 2, lB = lA + 1;
    const int bA = b0 + lA, bB = b0 + lB;
    const int jcol = j0 + jp * 2;

    int maxlen = 0;
    for (int i = 0; i < 16; i++) { int L = lens[b0 + i]; if (L > maxlen) maxlen = L; }
    const int LA = lens[bA], LB = lens[bB];

    // remote hbuf base addresses for all 8 cluster ranks
    uint32_t hb_rem[8];
    #pragma unroll
    for (int r = 0; r < 8; r++) hb_rem[r] = mapa_u32(smb + HB_BYTES, (uint32_t)r);

    float cA0 = 0.f, cA1 = 0.f, cB0 = 0.f, cB1 = 0.f;
    float hA0 = 0.f, hA1 = 0.f, hB0 = 0.f, hB1 = 0.f;
    uint32_t ph[2] = {0u, 0u};

    const ulonglong2* w0p = (const ulonglong2*)(Wp + (size_t)(jp)      * 516 + kh * 256);
    const ulonglong2* w1p = (const ulonglong2*)(Wp + (size_t)(16 + jp) * 516 + kh * 256);
    const ulonglong2* w2p = (const ulonglong2*)(Wp + (size_t)(32 + jp) * 516 + kh * 256);
    const ulonglong2* w3p = (const ulonglong2*)(Wp + (size_t)(48 + jp) * 516 + kh * 256);
    const float2* hApb = (const float2*)(Hb + (size_t)lA * 260 + kh * 128);
    const float2* hBpb = (const float2*)(Hb + (size_t)lB * 260 + kh * 128);

    for (int t = 0; t < maxlen; t++) {
        const int rb = t & 1, wb = (t + 1) & 1;

        // ---- prefetch gate pre-activations (kh==0 does the epilogue) ----
        float2 pxA0, pxA1, pxA2, pxA3, pxB0, pxB1, pxB2, pxB3;
        int posA = 0, posB = 0;
        const bool vA = (t < LA), vB = (t < LB);
        if (kh == 0) {
            if (vA) {
                posA = d ? (LA - 1 - t) : t;
                const float2* p = (const float2*)(P + (size_t)wid[bA * T + posA] * 1024) + (j0 >> 1) + jp;
                pxA0 = __ldg(p); pxA1 = __ldg(p + 128); pxA2 = __ldg(p + 256); pxA3 = __ldg(p + 384);
            }
            if (vB) {
                posB = d ? (LB - 1 - t) : t;
                const float2* p = (const float2*)(P + (size_t)wid[bB * T + posB] * 1024) + (j0 >> 1) + jp;
                pxB0 = __ldg(p); pxB1 = __ldg(p + 128); pxB2 = __ldg(p + 256); pxB3 = __ldg(p + 384);
            }
        }

        // ---- wait for all 8 CTAs' h(t-1) (DSMEM-delivered into hbuf[rb]) ----
        if (t > 0) { mbar_wait(mbA[rb], ph[rb]); ph[rb] ^= 1u; }

        // ---- partial recurrent GEMM over this thread's k-half ----
        const int bo = rb * 2080;   // float2 offset of buffer rb
        ull a00 = 0, a01 = 0, a10 = 0, a11 = 0, a20 = 0, a21 = 0, a30 = 0, a31 = 0;
        #pragma unroll 4
        for (int k2 = 0; k2 < 64; k2++) {
            ulonglong2 w0 = w0p[k2];
            ulonglong2 w1 = w1p[k2];
            ulonglong2 w2 = w2p[k2];
            ulonglong2 w3 = w3p[k2];
            float2 hA = hApb[bo + k2];
            float2 hB = hBpb[bo + k2];
            ull hA0_ = pack2(hA.x, hA.x), hA1_ = pack2(hA.y, hA.y);
            ull hB0_ = pack2(hB.x, hB.x), hB1_ = pack2(hB.y, hB.y);
            a00 = fma2(w0.x, hA0_, a00);
            a10 = fma2(w1.x, hA0_, a10);
            a20 = fma2(w2.x, hA0_, a20);
            a30 = fma2(w3.x, hA0_, a30);
            a01 = fma2(w0.x, hB0_, a01);
            a11 = fma2(w1.x, hB0_, a11);
            a21 = fma2(w2.x, hB0_, a21);
            a31 = fma2(w3.x, hB0_, a31);
            a00 = fma2(w0.y, hA1_, a00);
            a10 = fma2(w1.y, hA1_, a10);
            a20 = fma2(w2.y, hA1_, a20);
            a30 = fma2(w3.y, hA1_, a30);
            a01 = fma2(w0.y, hB1_, a01);
            a11 = fma2(w1.y, hB1_, a11);
            a21 = fma2(w2.y, hB1_, a21);
            a31 = fma2(w3.y, hB1_, a31);
        }

        // ---- cross-half reduction ----
        if (kh) {
            ulonglong2* rp = (ulonglong2*)(Red + (size_t)tl * 10);
            ulonglong2 v0; v0.x = a00; v0.y = a01;
            ulonglong2 v1; v1.x = a10; v1.y = a11;
            ulonglong2 v2; v2.x = a20; v2.y = a21;
            ulonglong2 v3; v3.x = a30; v3.y = a31;
            rp[0] = v0; rp[1] = v1; rp[2] = v2; rp[3] = v3;
        }
        __syncthreads();

        // ---- gates + publish via DSMEM (kh==0 only) ----
        if (kh == 0) {
            const ulonglong2* rp = (const ulonglong2*)(Red + (size_t)tl * 10);
            ulonglong2 r0 = rp[0], r1 = rp[1], r2 = rp[2], r3 = rp[3];
            a00 = add2(a00, r0.x); a01 = add2(a01, r0.y);
            a10 = add2(a10, r1.x); a11 = add2(a11, r1.y);
            a20 = add2(a20, r2.x); a21 = add2(a21, r2.y);
            a30 = add2(a30, r3.x); a31 = add2(a31, r3.y);

            if (vA) {
                float gi0, gi1, gf0, gf1, gg0, gg1, go0, go1;
                unpack2(a00, gi0, gi1); unpack2(a10, gf0, gf1);
                unpack2(a20, gg0, gg1); unpack2(a30, go0, go1);
                float i0 = sigf (gi0 + pxA0.x), i1 = sigf (gi1 + pxA0.y);
                float f0 = sigf (gf0 + pxA1.x), f1 = sigf (gf1 + pxA1.y);
                float g0 = tanhf(gg0 + pxA2.x), g1 = tanhf(gg1 + pxA2.y);
                float o0 = sigf (go0 + pxA3.x), o1 = sigf (go1 + pxA3.y);
                cA0 = f0 * cA0 + i0 * g0;
                cA1 = f1 * cA1 + i1 * g1;
                hA0 = o0 * tanhf(cA0); hA1 = o1 * tanhf(cA1);
                float2 hv; hv.x = hA0; hv.y = hA1;
                *(float2*)&g_Hc[((size_t)bA * T + posA) * (2 * H) + d * H + jcol] = hv;
            }
            if (vB) {
                float gi0, gi1, gf0, gf1, gg0, gg1, go0, go1;
                unpack2(a01, gi0, gi1); unpack2(a11, gf0, gf1);
                unpack2(a21, gg0, gg1); unpack2(a31, go0, go1);
                float i0 = sigf (gi0 + pxB0.x), i1 = sigf (gi1 + pxB0.y);
                float f0 = sigf (gf0 + pxB1.x), f1 = sigf (gf1 + pxB1.y);
                float g0 = tanhf(gg0 + pxB2.x), g1 = tanhf(gg1 + pxB2.y);
                float o0 = sigf (go0 + pxB3.x), o1 = sigf (go1 + pxB3.y);
                cB0 = f0 * cB0 + i0 * g0;
                cB1 = f1 * cB1 + i1 * g1;
                hB0 = o0 * tanhf(cB0); hB1 = o1 * tanhf(cB1);
                float2 hv; hv.x = hB0; hv.y = hB1;
                *(float2*)&g_Hc[((size_t)bB * T + posB) * (2 * H) + d * H + jcol] = hv;
            }

            // publish h (frozen batches re-send last value) to all 8 cluster CTAs
            const uint32_t off  = (uint32_t)(wb * 16640 + lA * 1040 + jcol * 4);
            const ull hAv = pack2(hA0, hA1);
            const ull hBv = pack2(hB0, hB1);
            #pragma unroll
            for (int r = 0; r < 8; r++) {
                st_cluster_b64(hb_rem[r] + off, hAv);
                st_cluster_b64(hb_rem[r] + off + 1040, hBv);
            }
        }

        // ---- arrive: all this CTA's stores are done -> one release per peer ----
        __syncthreads();
        if (tid < 8)
            mbar_arrive_remote(hb_rem[tid] - HB_BYTES + (uint32_t)(wb * 8));
    }

    CLUSTER_SYNC();   // no CTA exits while peers' DSMEM ops may be in flight
}

// ---------------- attention scores: s = tanh(Hc W_s1^T) W_s2^T ------
__global__ void k_scores(const float* __restrict__ Ws1, const float* __restrict__ Ws2)
{
    extern __shared__ float s2[];
    float* Ws  = s2;            // 25*512 = 12800
    float* raw = s2 + 12800;    // 32*25 = 800
    float* usm = s2 + 13600;    // 800

    const int tid = threadIdx.x;
    const int b  = blockIdx.x >> 4;
    const int t0 = (blockIdx.x & 15) * 32;

    for (int i = tid; i < 12800; i += 512) Ws[i] = Ws1[i];
    __syncthreads();

    const int wp = tid >> 5, lane = tid & 31;
    float acc0[DA] = {}, acc1[DA] = {};
    const float* hc0 = g_Hc + ((size_t)b * T + t0 + wp * 2) * 512;
    #pragma unroll 4
    for (int kk = 0; kk < 16; kk++) {
        int k = lane + kk * 32;
        float h0 = hc0[k];
        float h1 = hc0[512 + k];
        #pragma unroll
        for (int a = 0; a < DA; a++) {
            float w = Ws[a * 512 + k];
            acc0[a] = fmaf(h0, w, acc0[a]);
            acc1[a] = fmaf(h1, w, acc1[a]);
        }
    }
    #pragma unroll
    for (int a = 0; a < DA; a++) {
        float v0 = acc0[a], v1 = acc1[a];
        #pragma unroll
        for (int off = 16; off; off >>= 1) {
            v0 += __shfl_xor_sync(0xffffffffu, v0, off);
            v1 += __shfl_xor_sync(0xffffffffu, v1, off);
        }
        if (lane == 0) {
            raw[(wp * 2 + 0) * DA + a] = v0;
            raw[(wp * 2 + 1) * DA + a] = v1;
        }
    }
    __syncthreads();
    for (int i = tid; i < 32 * DA; i += 512) usm[i] = tanhf(raw[i]);
    __syncthreads();
    if (tid < 32 * HEADS) {
        int r = tid / HEADS, h = tid % HEADS;
        float s = 0.f;
        #pragma unroll
        for (int a = 0; a < DA; a++) s = fmaf(usm[r * DA + a], __ldg(&Ws2[h * DA + a]), s);
        g_s[((size_t)b * HEADS + h) * T + t0 + r] = s;
    }
}

// ---------------- masked softmax over time, per (b,head) ------------
__global__ void k_softmax(const int* __restrict__ lens)
{
    int b = blockIdx.x / HEADS, h = blockIdx.x % HEADS;
    int t = threadIdx.x;               // 512
    int L = lens[b];
    __shared__ float red[512];
    float sv = (t < L) ? g_s[((size_t)b * HEADS + h) * T + t] : -3.0e38f;
    red[t] = sv; __syncthreads();
    for (int off = 256; off; off >>= 1) { if (t < off) red[t] = fmaxf(red[t], red[t + off]); __syncthreads(); }
    float m = red[0]; __syncthreads();
    float e = (t < L) ? expf(sv - m) : 0.0f;
    red[t] = e; __syncthreads();
    for (int off = 256; off; off >>= 1) { if (t < off) red[t] += red[t + off]; __syncthreads(); }
    g_A[((size_t)b * HEADS + h) * T + t] = e / red[0];
}

// ---------------- M = A @ Hc  ->  sentence embeddings ---------------
__global__ void k_M(float* __restrict__ out)
{
    int b = blockIdx.x;
    int d = threadIdx.x;               // 512
    __shared__ float As[HEADS * T];
    for (int i = d; i < HEADS * T; i += 512) As[i] = g_A[(size_t)b * HEADS * T + i];
    __syncthreads();
    float acc[HEADS] = {};
    const float* hcb = g_Hc + (size_t)b * T * 512;
    for (int t = 0; t < T; t++) {
        float hc = hcb[(size_t)t * 512 + d];
        #pragma unroll
        for (int h = 0; h < HEADS; h++) acc[h] = fmaf(As[h * T + t], hc, acc[h]);
    }
    #pragma unroll
    for (int h = 0; h < HEADS; h++)
        out[(size_t)b * (HEADS * 2 * H) + h * 512 + d] = acc[h];
}

// ---------------- penalty -------------------------------------------
__global__ void k_penal1()
{
    int b = blockIdx.x;
    int tid = threadIdx.x;             // 256
    __shared__ float As[HEADS * T];
    __shared__ float red[256];
    for (int i = tid; i < HEADS * T; i += 256) As[i] = g_A[(size_t)b * HEADS * T + i];
    __syncthreads();
    float tot = 0.0f;
    for (int h = 0; h < HEADS; h++) {
        for (int g = 0; g < HEADS; g++) {
            if (h == g) continue;
            float p = 0.0f;
            for (int t = tid; t < T; t += 256) p = fmaf(As[h * T + t], As[g * T + t], p);
            red[tid] = p; __syncthreads();
            for (int off = 128; off; off >>= 1) { if (tid < off) red[tid] += red[tid + off]; __syncthreads(); }
            if (tid == 0) tot += red[0] * red[0];
            __syncthreads();
        }
    }
    if (tid == 0) g_pp[b] = tot;
}

__global__ void k_penal2(float* __restrict__ out, int out_size)
{
    __shared__ float red[128];
    red[threadIdx.x] = g_pp[threadIdx.x];
    __syncthreads();
    for (int off = 64; off; off >>= 1) { if (threadIdx.x < off) red[threadIdx.x] += red[threadIdx.x + off]; __syncthreads(); }
    if (threadIdx.x == 0) out[out_size - 1] = red[0] / (float)B;
}

// ---------------- launch --------------------------------------------
extern "C" void kernel_launch(void* const* d_in, const int* in_sizes, int n_in,
                              void* d_out, int out_size)
{
    const int*   word_ids = (const int*)  d_in[0];
    const int*   lens     = (const int*)  d_in[1];
    const float* emb      = (const float*)d_in[2];
    const float* Wihf     = (const float*)d_in[3];
    const float* Whhf     = (const float*)d_in[4];
    const float* bf       = (const float*)d_in[5];
    const float* Wihb     = (const float*)d_in[6];
    const float* Whhb     = (const float*)d_in[7];
    const float* bb       = (const float*)d_in[8];
    const float* Ws1      = (const float*)d_in[9];
    const float* Ws2      = (const float*)d_in[10];
    float* out = (float*)d_out;

    dim3 gP(16, (V + 63) / 64, 2);
    k_P<<<gP, 256>>>(emb, Wihf, bf, Wihb, bb);

    cudaFuncSetAttribute(k_lstm, cudaFuncAttributeMaxDynamicSharedMemorySize, 175632);
    k_lstm<<<128, 256, 175632>>>(Whhf, Whhb, lens, word_ids);

    cudaFuncSetAttribute(k_scores, cudaFuncAttributeMaxDynamicSharedMemorySize, 57600);
    k_scores<<<(B * T) / 32, 512, 57600>>>(Ws1, Ws2);

    k_softmax<<<B * HEADS, 512>>>(lens);
    k_M<<<B, 512>>>(out);
    k_penal1<<<B, 256>>>();
    k_penal2<<<1, 128>>>(out, out_size);
}

// round 7
// speedup vs baseline: 1.3952x; 1.3952x over previous
#include <cuda_runtime.h>
#include <math.h>
#include <stdint.h>

#define B 128
#define T 512
#define E 256
#define H 256
#define DA 25
#define HEADS 5
#define V 2080

typedef unsigned long long ull;

// ---------------- device scratch (static, no allocs) ----------------
__device__ float g_P[(size_t)2 * V * 1024];        // [dir][v][4H]  17MB (L2-resident)
__device__ float g_hstate[2 * 2 * B * H];          // [buf][dir][b][H]
__device__ float g_Hc[(size_t)B * T * 2 * H];      // [b][t][512]; tail stale-but-finite, masked by A=0
__device__ float g_s[B * HEADS * T];               // [b][h][t]
__device__ float g_A[B * HEADS * T];               // [b][h][t]
__device__ float g_pp[B];
__device__ unsigned g_bar[8];

// fast, overflow-safe sigmoid/tanh via MUFU.EX2 path (__expf)
__device__ __forceinline__ float sigf(float x) {
    return 1.0f / (1.0f + __expf(-x));           // x->-inf: expf->inf -> 0; x->+inf: -> 1
}
__device__ __forceinline__ float tanhfast(float x) {
    float ax = fabsf(x);
    float e = __expf(2.0f * ax);                 // ax large: e=inf -> t=1
    float t = 1.0f - 2.0f / (e + 1.0f);
    return copysignf(t, x);
}

__device__ __forceinline__ ull pack2(float lo, float hi) {
    ull r; asm("mov.b64 %0, {%1,%2};" : "=l"(r) : "f"(lo), "f"(hi)); return r;
}
__device__ __forceinline__ void unpack2(ull v, float& lo, float& hi) {
    asm("mov.b64 {%0,%1}, %2;" : "=f"(lo), "=f"(hi) : "l"(v));
}
__device__ __forceinline__ ull fma2(ull a, ull b, ull c) {
    ull d; asm("fma.rn.f32x2 %0, %1, %2, %3;" : "=l"(d) : "l"(a), "l"(b), "l"(c)); return d;
}
__device__ __forceinline__ ull add2(ull a, ull b) {
    ull d; asm("add.rn.f32x2 %0, %1, %2;" : "=l"(d) : "l"(a), "l"(b)); return d;
}

// ---------------- init: zero h buffers + barriers --------------------
__global__ void k_init() {
    size_t i = (size_t)blockIdx.x * blockDim.x + threadIdx.x;
    size_t stride = (size_t)gridDim.x * blockDim.x;
    for (size_t p = i; p < (size_t)2 * 2 * B * H; p += stride) g_hstate[p] = 0.0f;
    if (i < 8) g_bar[i] = 0u;
}

// ---------------- vocab projection: P[d][v][n] = emb[v] . W_ih[n] + b[n]
__global__ void k_P(const float* __restrict__ emb,
                    const float* __restrict__ Wf, const float* __restrict__ bf,
                    const float* __restrict__ Wb, const float* __restrict__ bb)
{
    const int d = blockIdx.z;
    const float* __restrict__ Wih  = d ? Wb : Wf;
    const float* __restrict__ bias = d ? bb : bf;
    const int n0 = blockIdx.x * 64;
    const int m0 = blockIdx.y * 64;

    __shared__ float As[16][68];
    __shared__ float Bs[16][68];

    const int tid = threadIdx.x;
    const int r  = tid >> 2, kq = tid & 3;
    const int tx = tid & 15, ty = tid >> 4;
    int v = m0 + r; if (v >= V) v = 0;
    const float* __restrict__ Arow = emb + (size_t)v * E;
    const float* __restrict__ Brow = Wih + (size_t)(n0 + r) * E;

    float acc[4][4] = {};

    for (int k0 = 0; k0 < E; k0 += 16) {
        float4 av = *(const float4*)&Arow[k0 + kq * 4];
        float4 bv = *(const float4*)&Brow[k0 + kq * 4];
        As[kq * 4 + 0][r] = av.x; As[kq * 4 + 1][r] = av.y;
        As[kq * 4 + 2][r] = av.z; As[kq * 4 + 3][r] = av.w;
        Bs[kq * 4 + 0][r] = bv.x; Bs[kq * 4 + 1][r] = bv.y;
        Bs[kq * 4 + 2][r] = bv.z; Bs[kq * 4 + 3][r] = bv.w;
        __syncthreads();
        #pragma unroll
        for (int kk = 0; kk < 16; kk++) {
            float4 a  = *(const float4*)&As[kk][ty * 4];
            float4 b4 = *(const float4*)&Bs[kk][tx * 4];
            acc[0][0] = fmaf(a.x, b4.x, acc[0][0]); acc[0][1] = fmaf(a.x, b4.y, acc[0][1]);
            acc[0][2] = fmaf(a.x, b4.z, acc[0][2]); acc[0][3] = fmaf(a.x, b4.w, acc[0][3]);
            acc[1][0] = fmaf(a.y, b4.x, acc[1][0]); acc[1][1] = fmaf(a.y, b4.y, acc[1][1]);
            acc[1][2] = fmaf(a.y, b4.z, acc[1][2]); acc[1][3] = fmaf(a.y, b4.w, acc[1][3]);
            acc[2][0] = fmaf(a.z, b4.x, acc[2][0]); acc[2][1] = fmaf(a.z, b4.y, acc[2][1]);
            acc[2][2] = fmaf(a.z, b4.z, acc[2][2]); acc[2][3] = fmaf(a.z, b4.w, acc[2][3]);
            acc[3][0] = fmaf(a.w, b4.x, acc[3][0]); acc[3][1] = fmaf(a.w, b4.y, acc[3][1]);
            acc[3][2] = fmaf(a.w, b4.z, acc[3][2]); acc[3][3] = fmaf(a.w, b4.w, acc[3][3]);
        }
        __syncthreads();
    }

    float b0v = bias[n0 + tx * 4 + 0];
    float b1v = bias[n0 + tx * 4 + 1];
    float b2v = bias[n0 + tx * 4 + 2];
    float b3v = bias[n0 + tx * 4 + 3];
    const size_t pbase = (size_t)d * V * 1024;
    #pragma unroll
    for (int i = 0; i < 4; i++) {
        int m = m0 + ty * 4 + i;
        if (m < V) {
            float4 o;
            o.x = acc[i][0] + b0v; o.y = acc[i][1] + b1v;
            o.z = acc[i][2] + b2v; o.w = acc[i][3] + b3v;
            *(float4*)&g_P[pbase + (size_t)m * 1024 + n0 + tx * 4] = o;
        }
    }
}

// ---------------- persistent LSTM recurrence ------------------------
// 128 blocks = 2 dirs * 16 j-tiles(16) * 4 batch-groups(32); 256 threads.
// thread = (kh, jp 0..7, bq 0..15): k-half split, 2 batches, j-pair (f32x2 over j).
__global__ void __launch_bounds__(256, 1)
k_lstm(const float* __restrict__ Whf, const float* __restrict__ Whb,
       const int* __restrict__ lens, const int* __restrict__ wid)
{
    extern __shared__ float sm[];
    float* Wp  = sm;                         // 16512 floats (66048 B)
    float* Hsh = sm + 16512;                 // 8320 floats  (33280 B)
    ull*   Red = (ull*)(sm + 24832);         // [128][10] ull (10240 B)

    const int tid = threadIdx.x;
    const int d   = blockIdx.x >> 6;
    const int rem = blockIdx.x & 63;
    const int jb  = rem >> 2, bg = rem & 3;
    const int j0  = jb * 16, b0 = bg * 32;
    const float* __restrict__ Whh = d ? Whb : Whf;
    const float* __restrict__ P   = g_P + (size_t)d * V * 1024;

    // W_hh tile -> shared, j-pair interleaved: Wp[(g*8+jp)*516 + k*2 + (j&1)]
    for (int idx = tid; idx < 16384; idx += 256) {
        int g = idx >> 12, j = (idx >> 8) & 15, k = idx & 255;
        Wp[(size_t)(g * 8 + (j >> 1)) * 516 + k * 2 + (j & 1)] =
            Whh[(size_t)(g * H + j0 + j) * H + k];
    }

    const int kh = tid >> 7;               // k-half: 0 -> k[0,128), 1 -> k[128,256)
    const int tl = tid & 127;
    const int jp = tl & 7, bq = tl >> 3;
    const int bA = b0 + bq * 2, bB = bA + 1;
    const int jcol = j0 + jp * 2;
    int maxlen = 0;
    for (int i = 0; i < 32; i++) { int L = lens[b0 + i]; if (L > maxlen) maxlen = L; }
    const int LA = lens[bA], LB = lens[bB];

    float cA0 = 0.f, cA1 = 0.f, cB0 = 0.f, cB1 = 0.f;
    unsigned* barp = &g_bar[d * 4 + bg];

    const ulonglong2* w0p = (const ulonglong2*)(Wp + (size_t)(jp)      * 516 + kh * 256);
    const ulonglong2* w1p = (const ulonglong2*)(Wp + (size_t)(8 + jp)  * 516 + kh * 256);
    const ulonglong2* w2p = (const ulonglong2*)(Wp + (size_t)(16 + jp) * 516 + kh * 256);
    const ulonglong2* w3p = (const ulonglong2*)(Wp + (size_t)(24 + jp) * 516 + kh * 256);
    const float2* hAp = (const float2*)(Hsh + (size_t)(bq * 2)     * 260 + kh * 128);
    const float2* hBp = (const float2*)(Hsh + (size_t)(bq * 2 + 1) * 260 + kh * 128);
    __syncthreads();

    for (int t = 0; t < maxlen; t++) {
        // ---- prefetch gate pre-activations (kh==0 threads do the epilogue) ----
        float2 pxA0, pxA1, pxA2, pxA3, pxB0, pxB1, pxB2, pxB3;
        int posA = 0, posB = 0;
        const bool vA = (t < LA), vB = (t < LB);
        if (kh == 0) {
            if (vA) {
                posA = d ? (LA - 1 - t) : t;
                const float2* p = (const float2*)(P + (size_t)wid[bA * T + posA] * 1024) + (j0 >> 1) + jp;
                pxA0 = __ldg(p); pxA1 = __ldg(p + 128); pxA2 = __ldg(p + 256); pxA3 = __ldg(p + 384);
            }
            if (vB) {
                posB = d ? (LB - 1 - t) : t;
                const float2* p = (const float2*)(P + (size_t)wid[bB * T + posB] * 1024) + (j0 >> 1) + jp;
                pxB0 = __ldg(p); pxB1 = __ldg(p + 128); pxB2 = __ldg(p + 256); pxB3 = __ldg(p + 384);
            }
        }

        // ---- h tile -> shared ----
        const int rb = t & 1;
        const float* hsrc = g_hstate + ((size_t)(rb * 2 + d) * B + b0) * H;
        #pragma unroll
        for (int q = 0; q < 8; q++) {
            int i = tid + q * 256; int r = i >> 6, cc = i & 63;
            float4 hv = __ldcg((const float4*)(hsrc + r * H + cc * 4));
            *(float4*)&Hsh[r * 260 + cc * 4] = hv;
        }
        __syncthreads();

        // ---- partial recurrent GEMM over this thread's k-half ----
        ull a00 = 0, a01 = 0, a10 = 0, a11 = 0, a20 = 0, a21 = 0, a30 = 0, a31 = 0;
        #pragma unroll 4
        for (int k2 = 0; k2 < 64; k2++) {
            ulonglong2 w0 = w0p[k2];
            ulonglong2 w1 = w1p[k2];
            ulonglong2 w2 = w2p[k2];
            ulonglong2 w3 = w3p[k2];
            float2 hA = hAp[k2];
            float2 hB = hBp[k2];
            ull hA0 = pack2(hA.x, hA.x), hA1 = pack2(hA.y, hA.y);
            ull hB0 = pack2(hB.x, hB.x), hB1 = pack2(hB.y, hB.y);
            a00 = fma2(w0.x, hA0, a00);
            a10 = fma2(w1.x, hA0, a10);
            a20 = fma2(w2.x, hA0, a20);
            a30 = fma2(w3.x, hA0, a30);
            a01 = fma2(w0.x, hB0, a01);
            a11 = fma2(w1.x, hB0, a11);
            a21 = fma2(w2.x, hB0, a21);
            a31 = fma2(w3.x, hB0, a31);
            a00 = fma2(w0.y, hA1, a00);
            a10 = fma2(w1.y, hA1, a10);
            a20 = fma2(w2.y, hA1, a20);
            a30 = fma2(w3.y, hA1, a30);
            a01 = fma2(w0.y, hB1, a01);
            a11 = fma2(w1.y, hB1, a11);
            a21 = fma2(w2.y, hB1, a21);
            a31 = fma2(w3.y, hB1, a31);
        }

        // ---- cross-half reduction ----
        if (kh) {
            ulonglong2* rp = (ulonglong2*)(Red + (size_t)tl * 10);
            ulonglong2 v0; v0.x = a00; v0.y = a01;
            ulonglong2 v1; v1.x = a10; v1.y = a11;
            ulonglong2 v2; v2.x = a20; v2.y = a21;
            ulonglong2 v3; v3.x = a30; v3.y = a31;
            rp[0] = v0; rp[1] = v1; rp[2] = v2; rp[3] = v3;
        }
        __syncthreads();

        // ---- gates + publish (kh==0 only) ----
        const int wb = (t + 1) & 1;
        if (kh == 0) {
            const ulonglong2* rp = (const ulonglong2*)(Red + (size_t)tl * 10);
            ulonglong2 r0 = rp[0], r1 = rp[1], r2 = rp[2], r3 = rp[3];
            a00 = add2(a00, r0.x); a01 = add2(a01, r0.y);
            a10 = add2(a10, r1.x); a11 = add2(a11, r1.y);
            a20 = add2(a20, r2.x); a21 = add2(a21, r2.y);
            a30 = add2(a30, r3.x); a31 = add2(a31, r3.y);

            if (vA) {
                float gi0, gi1, gf0, gf1, gg0, gg1, go0, go1;
                unpack2(a00, gi0, gi1); unpack2(a10, gf0, gf1);
                unpack2(a20, gg0, gg1); unpack2(a30, go0, go1);
                float i0 = sigf (gi0 + pxA0.x), i1 = sigf (gi1 + pxA0.y);
                float f0 = sigf (gf0 + pxA1.x), f1 = sigf (gf1 + pxA1.y);
                float g0 = tanhfast(gg0 + pxA2.x), g1 = tanhfast(gg1 + pxA2.y);
                float o0 = sigf (go0 + pxA3.x), o1 = sigf (go1 + pxA3.y);
                cA0 = f0 * cA0 + i0 * g0;
                cA1 = f1 * cA1 + i1 * g1;
                float2 hv; hv.x = o0 * tanhfast(cA0); hv.y = o1 * tanhfast(cA1);
                *(float2*)&g_hstate[((size_t)(wb * 2 + d) * B + bA) * H + jcol] = hv;
                *(float2*)&g_Hc[((size_t)bA * T + posA) * (2 * H) + d * H + jcol] = hv;
            }
            if (vB) {
                float gi0, gi1, gf0, gf1, gg0, gg1, go0, go1;
                unpack2(a01, gi0, gi1); unpack2(a11, gf0, gf1);
                unpack2(a21, gg0, gg1); unpack2(a31, go0, go1);
                float i0 = sigf (gi0 + pxB0.x), i1 = sigf (gi1 + pxB0.y);
                float f0 = sigf (gf0 + pxB1.x), f1 = sigf (gf1 + pxB1.y);
                float g0 = tanhfast(gg0 + pxB2.x), g1 = tanhfast(gg1 + pxB2.y);
                float o0 = sigf (go0 + pxB3.x), o1 = sigf (go1 + pxB3.y);
                cB0 = f0 * cB0 + i0 * g0;
                cB1 = f1 * cB1 + i1 * g1;
                float2 hv; hv.x = o0 * tanhfast(cB0); hv.y = o1 * tanhfast(cB1);
                *(float2*)&g_hstate[((size_t)(wb * 2 + d) * B + bB) * H + jcol] = hv;
                *(float2*)&g_Hc[((size_t)bB * T + posB) * (2 * H) + d * H + jcol] = hv;
            }
        }

        // ---- inter-block barrier: fence-free release/acquire ----
        // bar.sync orders all threads' prior STGs before tid0's cumulative release.
        __syncthreads();
        if (tid == 0) {
            asm volatile("red.release.gpu.global.add.u32 [%0], %1;" :: "l"(barp), "r"(1u) : "memory");
            unsigned target = 16u * (unsigned)(t + 1);
            unsigned v;
            do {
                asm volatile("ld.acquire.gpu.global.u32 %0, [%1];" : "=r"(v) : "l"(barp) : "memory");
            } while (v < target);
        }
        __syncthreads();
    }
}

// ---------------- attention scores: s = tanh(Hc W_s1^T) W_s2^T ------
__global__ void k_scores(const float* __restrict__ Ws1, const float* __restrict__ Ws2)
{
    extern __shared__ float s2[];
    float* Ws  = s2;            // 25*512 = 12800
    float* raw = s2 + 12800;    // 32*25 = 800
    float* usm = s2 + 13600;    // 800

    const int tid = threadIdx.x;
    const int b  = blockIdx.x >> 4;
    const int t0 = (blockIdx.x & 15) * 32;

    for (int i = tid; i < 12800; i += 512) Ws[i] = Ws1[i];
    __syncthreads();

    const int wp = tid >> 5, lane = tid & 31;   // warp wp -> rows 2wp, 2wp+1
    float acc0[DA] = {}, acc1[DA] = {};
    const float* hc0 = g_Hc + ((size_t)b * T + t0 + wp * 2) * 512;
    #pragma unroll 4
    for (int kk = 0; kk < 16; kk++) {
        int k = lane + kk * 32;
        float h0 = hc0[k];
        float h1 = hc0[512 + k];
        #pragma unroll
        for (int a = 0; a < DA; a++) {
            float w = Ws[a * 512 + k];
            acc0[a] = fmaf(h0, w, acc0[a]);
            acc1[a] = fmaf(h1, w, acc1[a]);
        }
    }
    #pragma unroll
    for (int a = 0; a < DA; a++) {
        float v0 = acc0[a], v1 = acc1[a];
        #pragma unroll
        for (int off = 16; off; off >>= 1) {
            v0 += __shfl_xor_sync(0xffffffffu, v0, off);
            v1 += __shfl_xor_sync(0xffffffffu, v1, off);
        }
        if (lane == 0) {
            raw[(wp * 2 + 0) * DA + a] = v0;
            raw[(wp * 2 + 1) * DA + a] = v1;
        }
    }
    __syncthreads();
    for (int i = tid; i < 32 * DA; i += 512) usm[i] = tanhf(raw[i]);
    __syncthreads();
    if (tid < 32 * HEADS) {
        int r = tid / HEADS, h = tid % HEADS;
        float s = 0.f;
        #pragma unroll
        for (int a = 0; a < DA; a++) s = fmaf(usm[r * DA + a], __ldg(&Ws2[h * DA + a]), s);
        g_s[((size_t)b * HEADS + h) * T + t0 + r] = s;
    }
}

// ---------------- masked softmax over time, per (b,head) ------------
__global__ void k_softmax(const int* __restrict__ lens)
{
    int b = blockIdx.x / HEADS, h = blockIdx.x % HEADS;
    int t = threadIdx.x;               // 512
    int L = lens[b];
    __shared__ float red[512];
    float sv = (t < L) ? g_s[((size_t)b * HEADS + h) * T + t] : -3.0e38f;
    red[t] = sv; __syncthreads();
    for (int off = 256; off; off >>= 1) { if (t < off) red[t] = fmaxf(red[t], red[t + off]); __syncthreads(); }
    float m = red[0]; __syncthreads();
    float e = (t < L) ? expf(sv - m) : 0.0f;
    red[t] = e; __syncthreads();
    for (int off = 256; off; off >>= 1) { if (t < off) red[t] += red[t + off]; __syncthreads(); }
    g_A[((size_t)b * HEADS + h) * T + t] = e / red[0];
}

// ---------------- M = A @ Hc  ->  sentence embeddings ---------------
__global__ void k_M(float* __restrict__ out)
{
    int b = blockIdx.x;
    int d = threadIdx.x;               // 512
    __shared__ float As[HEADS * T];
    for (int i = d; i < HEADS * T; i += 512) As[i] = g_A[(size_t)b * HEADS * T + i];
    __syncthreads();
    float acc[HEADS] = {};
    const float* hcb = g_Hc + (size_t)b * T * 512;
    for (int t = 0; t < T; t++) {
        float hc = hcb[(size_t)t * 512 + d];
        #pragma unroll
        for (int h = 0; h < HEADS; h++) acc[h] = fmaf(As[h * T + t], hc, acc[h]);
    }
    #pragma unroll
    for (int h = 0; h < HEADS; h++)
        out[(size_t)b * (HEADS * 2 * H) + h * 512 + d] = acc[h];
}

// ---------------- penalty -------------------------------------------
__global__ void k_penal1()
{
    int b = blockIdx.x;
    int tid = threadIdx.x;             // 256
    __shared__ float As[HEADS * T];
    __shared__ float red[256];
    for (int i = tid; i < HEADS * T; i += 256) As[i] = g_A[(size_t)b * HEADS * T + i];
    __syncthreads();
    float tot = 0.0f;
    for (int h = 0; h < HEADS; h++) {
        for (int g = 0; g < HEADS; g++) {
            if (h == g) continue;
            float p = 0.0f;
            for (int t = tid; t < T; t += 256) p = fmaf(As[h * T + t], As[g * T + t], p);
            red[tid] = p; __syncthreads();
            for (int off = 128; off; off >>= 1) { if (tid < off) red[tid] += red[tid + off]; __syncthreads(); }
            if (tid == 0) tot += red[0] * red[0];
            __syncthreads();
        }
    }
    if (tid == 0) g_pp[b] = tot;
}

__global__ void k_penal2(float* __restrict__ out, int out_size)
{
    __shared__ float red[128];
    red[threadIdx.x] = g_pp[threadIdx.x];
    __syncthreads();
    for (int off = 64; off; off >>= 1) { if (threadIdx.x < off) red[threadIdx.x] += red[threadIdx.x + off]; __syncthreads(); }
    if (threadIdx.x == 0) out[out_size - 1] = red[0] / (float)B;
}

// ---------------- launch --------------------------------------------
extern "C" void kernel_launch(void* const* d_in, const int* in_sizes, int n_in,
                              void* d_out, int out_size)
{
    const int*   word_ids = (const int*)  d_in[0];
    const int*   lens     = (const int*)  d_in[1];
    const float* emb      = (const float*)d_in[2];
    const float* Wihf     = (const float*)d_in[3];
    const float* Whhf     = (const float*)d_in[4];
    const float* bf       = (const float*)d_in[5];
    const float* Wihb     = (const float*)d_in[6];
    const float* Whhb     = (const float*)d_in[7];
    const float* bb       = (const float*)d_in[8];
    const float* Ws1      = (const float*)d_in[9];
    const float* Ws2      = (const float*)d_in[10];
    float* out = (float*)d_out;

    k_init<<<64, 256>>>();

    dim3 gP(16, (V + 63) / 64, 2);
    k_P<<<gP, 256>>>(emb, Wihf, bf, Wihb, bb);

    cudaFuncSetAttribute(k_lstm, cudaFuncAttributeMaxDynamicSharedMemorySize, 109568);
    k_lstm<<<128, 256, 109568>>>(Whhf, Whhb, lens, word_ids);

    cudaFuncSetAttribute(k_scores, cudaFuncAttributeMaxDynamicSharedMemorySize, 57600);
    k_scores<<<(B * T) / 32, 512, 57600>>>(Ws1, Ws2);

    k_softmax<<<B * HEADS, 512>>>(lens);
    k_M<<<B, 512>>>(out);
    k_penal1<<<B, 256>>>();
    k_penal2<<<1, 128>>>(out, out_size);
}

// round 8
// speedup vs baseline: 1.5448x; 1.1073x over previous
#include <cuda_runtime.h>
#include <math.h>
#include <stdint.h>

#define B 128
#define T 512
#define E 256
#define H 256
#define DA 25
#define HEADS 5
#define V 2080

typedef unsigned long long ull;

// ---------------- device scratch (static, no allocs) ----------------
__device__ float g_P[(size_t)2 * V * 1024];        // [dir][v][4H]  17MB (L2-resident)
__device__ float g_hstate[2 * 2 * B * H];          // [buf][dir][b][H]
__device__ float g_Hc[(size_t)B * T * 2 * H];      // [b][t][512]; tail stale-but-finite, masked by A=0
__device__ float g_s[B * HEADS * T];               // [b][h][t]
__device__ float g_A[B * HEADS * T];               // [b][h][t]
__device__ float g_pp[B];
__device__ unsigned g_bar[8];

// fast, overflow-safe sigmoid/tanh via MUFU.EX2 path (__expf)
__device__ __forceinline__ float sigf(float x) {
    return 1.0f / (1.0f + __expf(-x));
}
__device__ __forceinline__ float tanhfast(float x) {
    float ax = fabsf(x);
    float e = __expf(2.0f * ax);
    float t = 1.0f - 2.0f / (e + 1.0f);
    return copysignf(t, x);
}

__device__ __forceinline__ ull pack2(float lo, float hi) {
    ull r; asm("mov.b64 %0, {%1,%2};" : "=l"(r) : "f"(lo), "f"(hi)); return r;
}
__device__ __forceinline__ void unpack2(ull v, float& lo, float& hi) {
    asm("mov.b64 {%0,%1}, %2;" : "=f"(lo), "=f"(hi) : "l"(v));
}
__device__ __forceinline__ ull fma2(ull a, ull b, ull c) {
    ull d; asm("fma.rn.f32x2 %0, %1, %2, %3;" : "=l"(d) : "l"(a), "l"(b), "l"(c)); return d;
}
__device__ __forceinline__ ull add2(ull a, ull b) {
    ull d; asm("add.rn.f32x2 %0, %1, %2;" : "=l"(d) : "l"(a), "l"(b)); return d;
}

// ---------------- init: zero h buffers + barriers --------------------
__global__ void k_init() {
    size_t i = (size_t)blockIdx.x * blockDim.x + threadIdx.x;
    size_t stride = (size_t)gridDim.x * blockDim.x;
    for (size_t p = i; p < (size_t)2 * 2 * B * H; p += stride) g_hstate[p] = 0.0f;
    if (i < 8) g_bar[i] = 0u;
}

// ---------------- vocab projection: P[d][v][n] = emb[v] . W_ih[n] + b[n]
__global__ void k_P(const float* __restrict__ emb,
                    const float* __restrict__ Wf, const float* __restrict__ bf,
                    const float* __restrict__ Wb, const float* __restrict__ bb)
{
    const int d = blockIdx.z;
    const float* __restrict__ Wih  = d ? Wb : Wf;
    const float* __restrict__ bias = d ? bb : bf;
    const int n0 = blockIdx.x * 64;
    const int m0 = blockIdx.y * 64;

    __shared__ float As[16][68];
    __shared__ float Bs[16][68];

    const int tid = threadIdx.x;
    const int r  = tid >> 2, kq = tid & 3;
    const int tx = tid & 15, ty = tid >> 4;
    int v = m0 + r; if (v >= V) v = 0;
    const float* __restrict__ Arow = emb + (size_t)v * E;
    const float* __restrict__ Brow = Wih + (size_t)(n0 + r) * E;

    float acc[4][4] = {};

    for (int k0 = 0; k0 < E; k0 += 16) {
        float4 av = *(const float4*)&Arow[k0 + kq * 4];
        float4 bv = *(const float4*)&Brow[k0 + kq * 4];
        As[kq * 4 + 0][r] = av.x; As[kq * 4 + 1][r] = av.y;
        As[kq * 4 + 2][r] = av.z; As[kq * 4 + 3][r] = av.w;
        Bs[kq * 4 + 0][r] = bv.x; Bs[kq * 4 + 1][r] = bv.y;
        Bs[kq * 4 + 2][r] = bv.z; Bs[kq * 4 + 3][r] = bv.w;
        __syncthreads();
        #pragma unroll
        for (int kk = 0; kk < 16; kk++) {
            float4 a  = *(const float4*)&As[kk][ty * 4];
            float4 b4 = *(const float4*)&Bs[kk][tx * 4];
            acc[0][0] = fmaf(a.x, b4.x, acc[0][0]); acc[0][1] = fmaf(a.x, b4.y, acc[0][1]);
            acc[0][2] = fmaf(a.x, b4.z, acc[0][2]); acc[0][3] = fmaf(a.x, b4.w, acc[0][3]);
            acc[1][0] = fmaf(a.y, b4.x, acc[1][0]); acc[1][1] = fmaf(a.y, b4.y, acc[1][1]);
            acc[1][2] = fmaf(a.y, b4.z, acc[1][2]); acc[1][3] = fmaf(a.y, b4.w, acc[1][3]);
            acc[2][0] = fmaf(a.z, b4.x, acc[2][0]); acc[2][1] = fmaf(a.z, b4.y, acc[2][1]);
            acc[2][2] = fmaf(a.z, b4.z, acc[2][2]); acc[2][3] = fmaf(a.z, b4.w, acc[2][3]);
            acc[3][0] = fmaf(a.w, b4.x, acc[3][0]); acc[3][1] = fmaf(a.w, b4.y, acc[3][1]);
            acc[3][2] = fmaf(a.w, b4.z, acc[3][2]); acc[3][3] = fmaf(a.w, b4.w, acc[3][3]);
        }
        __syncthreads();
    }

    float b0v = bias[n0 + tx * 4 + 0];
    float b1v = bias[n0 + tx * 4 + 1];
    float b2v = bias[n0 + tx * 4 + 2];
    float b3v = bias[n0 + tx * 4 + 3];
    const size_t pbase = (size_t)d * V * 1024;
    #pragma unroll
    for (int i = 0; i < 4; i++) {
        int m = m0 + ty * 4 + i;
        if (m < V) {
            float4 o;
            o.x = acc[i][0] + b0v; o.y = acc[i][1] + b1v;
            o.z = acc[i][2] + b2v; o.w = acc[i][3] + b3v;
            *(float4*)&g_P[pbase + (size_t)m * 1024 + n0 + tx * 4] = o;
        }
    }
}

// ---------------- persistent LSTM recurrence ------------------------
// 128 blocks = 2 dirs * 16 j-tiles(16 j) * 4 batch-groups(32 b); 256 threads.
// Compute role: warp (kq 0..3, gh 0..1), lane (j 0..15, gl 0..1). Each thread
// owns W row (g = gh*2+gl, j0+j) over k-slice [kq*64, kq*64+64) IN REGISTERS
// (32 f32x2 k-pairs). h read via warp-broadcast LDS.128. Partials reduced
// over kq through a padded smem buffer.
// Epilogue role: thread (jp 0..7, bq 0..31) -> 1 batch, j-pair, gates + c-state.
__global__ void __launch_bounds__(256, 1)
k_lstm(const float* __restrict__ Whf, const float* __restrict__ Whb,
       const int* __restrict__ lens, const int* __restrict__ wid)
{
    extern __shared__ float sm[];
    float* Hsh = sm;               // [32][256] = 8192 floats (32 KB)
    float* Red = sm + 8192;        // [32*4 rows][68] = 8704 floats (34.8 KB)

    const int tid = threadIdx.x;
    const int d   = blockIdx.x >> 6;
    const int rem = blockIdx.x & 63;
    const int jb  = rem >> 2, bg = rem & 3;
    const int j0  = jb * 16, b0 = bg * 32;
    const float* __restrict__ Whh = d ? Whb : Whf;
    const float* __restrict__ P   = g_P + (size_t)d * V * 1024;

    // ---- compute-role indices ----
    const int warp = tid >> 5, lane = tid & 31;
    const int kq = warp & 3, gh = warp >> 2;
    const int jc = lane >> 1, gl = lane & 1;
    const int gc = gh * 2 + gl;

    // ---- W -> registers (k-pair packed f32x2) ----
    ull w2[32];
    {
        const float2* wrow = (const float2*)(Whh + (size_t)(gc * H + j0 + jc) * H + kq * 64);
        #pragma unroll
        for (int i = 0; i < 32; i++) {
            float2 wv = __ldg(&wrow[i]);
            w2[i] = pack2(wv.x, wv.y);
        }
    }

    // ---- epilogue-role indices ----
    const int jp = tid & 7, bq = tid >> 3;     // 8 x 32
    const int bE = b0 + bq;
    const int jcol = j0 + jp * 2;
    const int LE = lens[bE];
    int maxlen = 0;
    for (int i = 0; i < 32; i++) { int L = lens[b0 + i]; if (L > maxlen) maxlen = L; }

    float c0 = 0.f, c1 = 0.f;
    unsigned* barp = &g_bar[d * 4 + bg];

    for (int t = 0; t < maxlen; t++) {
        // ---- px prefetch (epilogue role; L2-resident P) ----
        float2 px0, px1, px2, px3;
        int pos = 0;
        const bool vE = (t < LE);
        if (vE) {
            pos = d ? (LE - 1 - t) : t;
            const float2* p = (const float2*)(P + (size_t)wid[bE * T + pos] * 1024) + (j0 >> 1) + jp;
            px0 = __ldg(p); px1 = __ldg(p + 128); px2 = __ldg(p + 256); px3 = __ldg(p + 384);
        }

        // ---- stage h tile (32 KB from L2) ----
        const int rb = t & 1;
        const float* hsrc = g_hstate + ((size_t)(rb * 2 + d) * B + b0) * H;
        #pragma unroll
        for (int q = 0; q < 8; q++) {
            int i = tid + q * 256; int r = i >> 6, cc = i & 63;
            float4 hv = __ldcg((const float4*)(hsrc + r * H + cc * 4));
            *(float4*)&Hsh[r * 256 + cc * 4] = hv;
        }
        __syncthreads();

        // ---- compute: W in regs, h broadcast; 2 batches per pass ----
        for (int bb = 0; bb < 16; bb++) {
            const ulonglong2* r0 = (const ulonglong2*)(Hsh + (2 * bb) * 256 + kq * 64);
            const ulonglong2* r1 = (const ulonglong2*)(Hsh + (2 * bb + 1) * 256 + kq * 64);
            ull a0e = 0, a0o = 0, a1e = 0, a1o = 0;
            #pragma unroll
            for (int k4 = 0; k4 < 16; k4++) {
                ulonglong2 h0 = r0[k4];
                ulonglong2 h1 = r1[k4];
                a0e = fma2(w2[2 * k4],     h0.x, a0e);
                a0o = fma2(w2[2 * k4 + 1], h0.y, a0o);
                a1e = fma2(w2[2 * k4],     h1.x, a1e);
                a1o = fma2(w2[2 * k4 + 1], h1.y, a1o);
            }
            ull a0 = add2(a0e, a0o), a1 = add2(a1e, a1o);
            float x0, y0, x1, y1;
            unpack2(a0, x0, y0); unpack2(a1, x1, y1);
            Red[((2 * bb)     * 4 + gc) * 68 + kq * 16 + jc] = x0 + y0;
            Red[((2 * bb + 1) * 4 + gc) * 68 + kq * 16 + jc] = x1 + y1;
        }
        __syncthreads();

        // ---- epilogue: reduce over kq, gates, publish ----
        const int wb = (t + 1) & 1;
        if (vE) {
            ull ag[4];
            #pragma unroll
            for (int g = 0; g < 4; g++) {
                const ull* rr = (const ull*)(Red + (size_t)(bq * 4 + g) * 68 + 2 * jp);
                ull v0 = rr[0], v1 = rr[8], v2 = rr[16], v3 = rr[24];
                ag[g] = add2(add2(v0, v1), add2(v2, v3));
            }
            float gi0, gi1, gf0, gf1, gg0, gg1, go0, go1;
            unpack2(ag[0], gi0, gi1); unpack2(ag[1], gf0, gf1);
            unpack2(ag[2], gg0, gg1); unpack2(ag[3], go0, go1);
            float i0 = sigf (gi0 + px0.x), i1 = sigf (gi1 + px0.y);
            float f0 = sigf (gf0 + px1.x), f1 = sigf (gf1 + px1.y);
            float g0 = tanhfast(gg0 + px2.x), g1 = tanhfast(gg1 + px2.y);
            float o0 = sigf (go0 + px3.x), o1 = sigf (go1 + px3.y);
            c0 = f0 * c0 + i0 * g0;
            c1 = f1 * c1 + i1 * g1;
            float2 hv; hv.x = o0 * tanhfast(c0); hv.y = o1 * tanhfast(c1);
            *(float2*)&g_hstate[((size_t)(wb * 2 + d) * B + bE) * H + jcol] = hv;
            *(float2*)&g_Hc[((size_t)bE * T + pos) * (2 * H) + d * H + jcol] = hv;
        }

        // ---- inter-block barrier: fence-free release/acquire (R7-proven) ----
        __syncthreads();
        if (tid == 0) {
            asm volatile("red.release.gpu.global.add.u32 [%0], %1;" :: "l"(barp), "r"(1u) : "memory");
            unsigned target = 16u * (unsigned)(t + 1);
            unsigned v;
            do {
                asm volatile("ld.acquire.gpu.global.u32 %0, [%1];" : "=r"(v) : "l"(barp) : "memory");
            } while (v < target);
        }
        __syncthreads();
    }
}

// ---------------- attention scores: s = tanh(Hc W_s1^T) W_s2^T ------
__global__ void k_scores(const float* __restrict__ Ws1, const float* __restrict__ Ws2)
{
    extern __shared__ float s2[];
    float* Ws  = s2;            // 25*512 = 12800
    float* raw = s2 + 12800;    // 32*25 = 800
    float* usm = s2 + 13600;    // 800

    const int tid = threadIdx.x;
    const int b  = blockIdx.x >> 4;
    const int t0 = (blockIdx.x & 15) * 32;

    for (int i = tid; i < 12800; i += 512) Ws[i] = Ws1[i];
    __syncthreads();

    const int wp = tid >> 5, lane = tid & 31;
    float acc0[DA] = {}, acc1[DA] = {};
    const float* hc0 = g_Hc + ((size_t)b * T + t0 + wp * 2) * 512;
    #pragma unroll 4
    for (int kk = 0; kk < 16; kk++) {
        int k = lane + kk * 32;
        float h0 = hc0[k];
        float h1 = hc0[512 + k];
        #pragma unroll
        for (int a = 0; a < DA; a++) {
            float w = Ws[a * 512 + k];
            acc0[a] = fmaf(h0, w, acc0[a]);
            acc1[a] = fmaf(h1, w, acc1[a]);
        }
    }
    #pragma unroll
    for (int a = 0; a < DA; a++) {
        float v0 = acc0[a], v1 = acc1[a];
        #pragma unroll
        for (int off = 16; off; off >>= 1) {
            v0 += __shfl_xor_sync(0xffffffffu, v0, off);
            v1 += __shfl_xor_sync(0xffffffffu, v1, off);
        }
        if (lane == 0) {
            raw[(wp * 2 + 0) * DA + a] = v0;
            raw[(wp * 2 + 1) * DA + a] = v1;
        }
    }
    __syncthreads();
    for (int i = tid; i < 32 * DA; i += 512) usm[i] = tanhf(raw[i]);
    __syncthreads();
    if (tid < 32 * HEADS) {
        int r = tid / HEADS, h = tid % HEADS;
        float s = 0.f;
        #pragma unroll
        for (int a = 0; a < DA; a++) s = fmaf(usm[r * DA + a], __ldg(&Ws2[h * DA + a]), s);
        g_s[((size_t)b * HEADS + h) * T + t0 + r] = s;
    }
}

// ---------------- masked softmax over time, per (b,head) ------------
__global__ void k_softmax(const int* __restrict__ lens)
{
    int b = blockIdx.x / HEADS, h = blockIdx.x % HEADS;
    int t = threadIdx.x;               // 512
    int L = lens[b];
    __shared__ float red[512];
    float sv = (t < L) ? g_s[((size_t)b * HEADS + h) * T + t] : -3.0e38f;
    red[t] = sv; __syncthreads();
    for (int off = 256; off; off >>= 1) { if (t < off) red[t] = fmaxf(red[t], red[t + off]); __syncthreads(); }
    float m = red[0]; __syncthreads();
    float e = (t < L) ? expf(sv - m) : 0.0f;
    red[t] = e; __syncthreads();
    for (int off = 256; off; off >>= 1) { if (t < off) red[t] += red[t + off]; __syncthreads(); }
    g_A[((size_t)b * HEADS + h) * T + t] = e / red[0];
}

// ---------------- M = A @ Hc  ->  sentence embeddings ---------------
__global__ void k_M(float* __restrict__ out)
{
    int b = blockIdx.x;
    int d = threadIdx.x;               // 512
    __shared__ float As[HEADS * T];
    for (int i = d; i < HEADS * T; i += 512) As[i] = g_A[(size_t)b * HEADS * T + i];
    __syncthreads();
    float acc[HEADS] = {};
    const float* hcb = g_Hc + (size_t)b * T * 512;
    for (int t = 0; t < T; t++) {
        float hc = hcb[(size_t)t * 512 + d];
        #pragma unroll
        for (int h = 0; h < HEADS; h++) acc[h] = fmaf(As[h * T + t], hc, acc[h]);
    }
    #pragma unroll
    for (int h = 0; h < HEADS; h++)
        out[(size_t)b * (HEADS * 2 * H) + h * 512 + d] = acc[h];
}

// ---------------- penalty -------------------------------------------
__global__ void k_penal1()
{
    int b = blockIdx.x;
    int tid = threadIdx.x;             // 256
    __shared__ float As[HEADS * T];
    __shared__ float red[256];
    for (int i = tid; i < HEADS * T; i += 256) As[i] = g_A[(size_t)b * HEADS * T + i];
    __syncthreads();
    float tot = 0.0f;
    for (int h = 0; h < HEADS; h++) {
        for (int g = 0; g < HEADS; g++) {
            if (h == g) continue;
            float p = 0.0f;
            for (int t = tid; t < T; t += 256) p = fmaf(As[h * T + t], As[g * T + t], p);
            red[tid] = p; __syncthreads();
            for (int off = 128; off; off >>= 1) { if (tid < off) red[tid] += red[tid + off]; __syncthreads(); }
            if (tid == 0) tot += red[0] * red[0];
            __syncthreads();
        }
    }
    if (tid == 0) g_pp[b] = tot;
}

__global__ void k_penal2(float* __restrict__ out, int out_size)
{
    __shared__ float red[128];
    red[threadIdx.x] = g_pp[threadIdx.x];
    __syncthreads();
    for (int off = 64; off; off >>= 1) { if (threadIdx.x < off) red[threadIdx.x] += red[threadIdx.x + off]; __syncthreads(); }
    if (threadIdx.x == 0) out[out_size - 1] = red[0] / (float)B;
}

// ---------------- launch --------------------------------------------
extern "C" void kernel_launch(void* const* d_in, const int* in_sizes, int n_in,
                              void* d_out, int out_size)
{
    const int*   word_ids = (const int*)  d_in[0];
    const int*   lens     = (const int*)  d_in[1];
    const float* emb      = (const float*)d_in[2];
    const float* Wihf     = (const float*)d_in[3];
    const float* Whhf     = (const float*)d_in[4];
    const float* bf       = (const float*)d_in[5];
    const float* Wihb     = (const float*)d_in[6];
    const float* Whhb     = (const float*)d_in[7];
    const float* bb       = (const float*)d_in[8];
    const float* Ws1      = (const float*)d_in[9];
    const float* Ws2      = (const float*)d_in[10];
    float* out = (float*)d_out;

    k_init<<<64, 256>>>();

    dim3 gP(16, (V + 63) / 64, 2);
    k_P<<<gP, 256>>>(emb, Wihf, bf, Wihb, bb);

    cudaFuncSetAttribute(k_lstm, cudaFuncAttributeMaxDynamicSharedMemorySize, 67584);
    k_lstm<<<128, 256, 67584>>>(Whhf, Whhb, lens, word_ids);

    cudaFuncSetAttribute(k_scores, cudaFuncAttributeMaxDynamicSharedMemorySize, 57600);
    k_scores<<<(B * T) / 32, 512, 57600>>>(Ws1, Ws2);

    k_softmax<<<B * HEADS, 512>>>(lens);
    k_M<<<B, 512>>>(out);
    k_penal1<<<B, 256>>>();
    k_penal2<<<1, 128>>>(out, out_size);
}